// round 15
// baseline (speedup 1.0000x reference)
#include <cuda_runtime.h>
#include <cuda_bf16.h>
#include <math.h>
#include <stdint.h>

// Fused transformer block on tensor cores (bf16 mma.sync, fp32 accum).
// R15: persistent CTAs (444 = 148 SMs x 3), each loops over ~9 batch tiles.
// Weight fragments become L1-resident after the first iteration (B300 keeps
// L1D within a launch), removing the per-CTA cold-start LDG latency and the
// inter-wave transitions. Per-tile math identical to R14.

#define T_ 64
#define C_ 64
#define EPS_ 1e-5f
#define PERSIST_CTAS (148 * 3)

// ---------------- pair-packed bf16 weight fragments (prologue) --------------
__device__ uint4 g_fqkv4[4 * 8 * 32];   // qkv nt pairs {3w, 3w+1} per warp w
__device__ uint2 g_fqkv2[4 * 8 * 32];   // qkv nt {3w+2}
__device__ uint4 g_fap4 [4 * 4 * 32];   // aproj nt pairs
__device__ uint4 g_ffc4 [4 * 16 * 32];  // fc nt pairs
__device__ uint4 g_fmp4 [16 * 4 * 32];  // mproj nt pairs

__device__ __forceinline__ uint32_t packbf(float x, float y) {
    __nv_bfloat162 h = __floats2bfloat162_rn(x, y);
    return *(uint32_t*)&h;
}

__device__ __forceinline__ uint2 make_frag(const float* __restrict__ W, int ld,
                                           int kt, int nt, int lane) {
    const int gid = lane >> 2, tig = lane & 3;
    const int k0 = kt * 16 + tig * 2, n = nt * 8 + gid;
    uint2 v;
    v.x = packbf(__ldg(W + k0 * ld + n), __ldg(W + (k0 + 1) * ld + n));
    v.y = packbf(__ldg(W + (k0 + 8) * ld + n), __ldg(W + (k0 + 9) * ld + n));
    return v;
}

__global__ void convert_weights_kernel(const float* __restrict__ qkv_w,
                                       const float* __restrict__ aproj_w,
                                       const float* __restrict__ fc_w,
                                       const float* __restrict__ mproj_w) {
    const int idx = blockIdx.x * blockDim.x + threadIdx.x;
    const int lane = idx & 31;
    if (idx < 1024) {
        const int rem = idx >> 5;
        const int kt = rem >> 3, w = rem & 7;
        const uint2 a = make_frag(qkv_w, 192, kt, w * 3 + 0, lane);
        const uint2 b = make_frag(qkv_w, 192, kt, w * 3 + 1, lane);
        g_fqkv4[idx] = make_uint4(a.x, a.y, b.x, b.y);
    } else if (idx < 2048) {
        const int i = idx - 1024;
        const int rem = i >> 5;
        const int kt = rem >> 3, w = rem & 7;
        g_fqkv2[i] = make_frag(qkv_w, 192, kt, w * 3 + 2, lane);
    } else if (idx < 2560) {
        const int i = idx - 2048;
        const int rem = i >> 5;
        const int kt = rem >> 2, p = rem & 3;
        const uint2 a = make_frag(aproj_w, 64, kt, p * 2 + 0, lane);
        const uint2 b = make_frag(aproj_w, 64, kt, p * 2 + 1, lane);
        g_fap4[i] = make_uint4(a.x, a.y, b.x, b.y);
    } else if (idx < 4608) {
        const int i = idx - 2560;
        const int rem = i >> 5;
        const int kt = rem >> 4, p = rem & 15;
        const uint2 a = make_frag(fc_w, 256, kt, p * 2 + 0, lane);
        const uint2 b = make_frag(fc_w, 256, kt, p * 2 + 1, lane);
        g_ffc4[i] = make_uint4(a.x, a.y, b.x, b.y);
    } else if (idx < 6656) {
        const int i = idx - 4608;
        const int rem = i >> 5;
        const int kt = rem >> 2, p = rem & 3;
        const uint2 a = make_frag(mproj_w, 64, kt, p * 2 + 0, lane);
        const uint2 b = make_frag(mproj_w, 64, kt, p * 2 + 1, lane);
        g_fmp4[i] = make_uint4(a.x, a.y, b.x, b.y);
    }
}

// ---------------- helpers ----------------------------------------------------
__device__ __forceinline__ uint32_t smem_u32(const void* p) {
    return (uint32_t)__cvta_generic_to_shared(p);
}
__device__ __forceinline__ void ldsm_x4(uint32_t a, uint32_t& r0, uint32_t& r1,
                                        uint32_t& r2, uint32_t& r3) {
    asm volatile("ldmatrix.sync.aligned.m8n8.x4.shared.b16 {%0,%1,%2,%3}, [%4];\n"
                 : "=r"(r0), "=r"(r1), "=r"(r2), "=r"(r3) : "r"(a));
}
__device__ __forceinline__ void ldsm_x4t(uint32_t a, uint32_t& r0, uint32_t& r1,
                                         uint32_t& r2, uint32_t& r3) {
    asm volatile("ldmatrix.sync.aligned.m8n8.x4.trans.shared.b16 {%0,%1,%2,%3}, [%4];\n"
                 : "=r"(r0), "=r"(r1), "=r"(r2), "=r"(r3) : "r"(a));
}
__device__ __forceinline__ void mma16816(float& d0, float& d1, float& d2, float& d3,
                                         uint32_t a0, uint32_t a1, uint32_t a2,
                                         uint32_t a3, uint32_t b0, uint32_t b1) {
    asm volatile(
        "mma.sync.aligned.m16n8k16.row.col.f32.bf16.bf16.f32 "
        "{%0,%1,%2,%3},{%4,%5,%6,%7},{%8,%9},{%0,%1,%2,%3};\n"
        : "+f"(d0), "+f"(d1), "+f"(d2), "+f"(d3)
        : "r"(a0), "r"(a1), "r"(a2), "r"(a3), "r"(b0), "r"(b1));
}
__device__ __forceinline__ float gelu_fast(float v) {
    float u = v * (0.7978845608f + 0.0356774081f * v * v);
    float th;
    asm("tanh.approx.f32 %0, %1;\n" : "=f"(th) : "f"(u));
    return 0.5f * v * (1.0f + th);
}

// smem: xs fp32 16384 | hb 64x72 bf16 9216 | act bf16 (qkv 64x200 / fc 64x264)
#define OFF_XS 0
#define OFF_HB 16384
#define OFF_ACT 25600
#define SMEM_BYTES (25600 + 64 * 264 * 2)   // 59392

__global__ __launch_bounds__(256, 3) void block_tc_kernel(
    const float* __restrict__ x,
    const float* __restrict__ ln1_g, const float* __restrict__ ln1_b,
    const float* __restrict__ qkv_b,
    const float* __restrict__ aproj_b,
    const float* __restrict__ ln2_g, const float* __restrict__ ln2_b,
    const float* __restrict__ fc_b,
    const float* __restrict__ mproj_b,
    float* __restrict__ out, int B) {
    extern __shared__ char smem[];
    float* xs = (float*)(smem + OFF_XS);
    __nv_bfloat16* hb = (__nv_bfloat16*)(smem + OFF_HB);      // stride 72
    __nv_bfloat16* qkvs = (__nv_bfloat16*)(smem + OFF_ACT);   // stride 200 / 264
    const uint32_t hb_a = smem_u32(hb);
    const uint32_t act_a = smem_u32(qkvs);

    const int tid = threadIdx.x;
    const int wid = tid >> 5;
    const int lane = tid & 31;
    const int g = lane >> 2;
    const int t = lane & 3;
    const int lr = lane & 15;             // ldsm row-in-tile
    const int lc = (lane >> 4) << 3;      // ldsm col offset
    const int mg = wid & 1;               // 2m x 2n partition (aproj)
    const int ng = wid >> 1;

    const int lrow = tid >> 2;            // LN row
    const int lcol = (tid & 3) * 16;      // LN col base

    for (int bid = blockIdx.x; bid < B; bid += PERSIST_CTAS) {
        const size_t base = (size_t)bid * (T_ * C_);
        const float* xg = x + base;
        float* og = out + base;

        // protect smem reuse against trailing mproj of previous iteration
        __syncthreads();

        // ---- PREFETCH: QKV B fragments + biases ----
        uint4 Bq4[4];
        uint2 Bq2[4];
        #pragma unroll
        for (int kt = 0; kt < 4; ++kt) {
            Bq4[kt] = __ldg(g_fqkv4 + ((kt * 8 + wid) << 5) + lane);
            Bq2[kt] = __ldg(g_fqkv2 + ((kt * 8 + wid) << 5) + lane);
        }
        float2 biasq[3];
        #pragma unroll
        for (int j = 0; j < 3; ++j)
            biasq[j] = *(const float2*)(qkv_b + (wid * 3 + j) * 8 + t * 2);

        // ---- LN1 fused with global x read: x -> regs -> xs + hb ----
        {
            const float4* srcg = (const float4*)(xg + lrow * 64 + lcol);
            float4 v4[4];
            float s = 0.f, s2 = 0.f;
            #pragma unroll
            for (int i = 0; i < 4; ++i) {
                v4[i] = srcg[i];
                s += v4[i].x + v4[i].y + v4[i].z + v4[i].w;
                s2 += v4[i].x * v4[i].x + v4[i].y * v4[i].y
                    + v4[i].z * v4[i].z + v4[i].w * v4[i].w;
            }
            s  += __shfl_xor_sync(0xffffffffu, s, 1);
            s2 += __shfl_xor_sync(0xffffffffu, s2, 1);
            s  += __shfl_xor_sync(0xffffffffu, s, 2);
            s2 += __shfl_xor_sync(0xffffffffu, s2, 2);
            const float mu = s * (1.0f / 64.0f);
            const float var = s2 * (1.0f / 64.0f) - mu * mu;
            const float rstd = rsqrtf(var + EPS_);
            const float* v = (const float*)v4;
            #pragma unroll
            for (int i = 0; i < 4; ++i) {
                *(float4*)(xs + lrow * 64 + lcol + 4 * i) = v4[i];
                const int c = lcol + 4 * i;
                uint2 u;
                u.x = packbf((v[4*i+0] - mu) * rstd * ln1_g[c+0] + ln1_b[c+0],
                             (v[4*i+1] - mu) * rstd * ln1_g[c+1] + ln1_b[c+1]);
                u.y = packbf((v[4*i+2] - mu) * rstd * ln1_g[c+2] + ln1_b[c+2],
                             (v[4*i+3] - mu) * rstd * ln1_g[c+3] + ln1_b[c+3]);
                *(uint2*)(hb + lrow * 72 + c) = u;
            }
        }
        __syncthreads();

        // ---- QKV: warp owns cols [24w, 24w+24), loops all 4 m-tiles ----
        {
            #pragma unroll
            for (int mt = 0; mt < 4; ++mt) {
                float d[3][4];
                #pragma unroll
                for (int j = 0; j < 3; ++j) {
                    d[j][0] = d[j][2] = biasq[j].x;
                    d[j][1] = d[j][3] = biasq[j].y;
                }
                #pragma unroll
                for (int kt = 0; kt < 4; ++kt) {
                    uint32_t a0, a1, a2, a3;
                    ldsm_x4(hb_a + (uint32_t)(((mt * 16 + lr) * 72 + kt * 16 + lc) * 2),
                            a0, a1, a2, a3);
                    mma16816(d[0][0], d[0][1], d[0][2], d[0][3],
                             a0, a1, a2, a3, Bq4[kt].x, Bq4[kt].y);
                    mma16816(d[1][0], d[1][1], d[1][2], d[1][3],
                             a0, a1, a2, a3, Bq4[kt].z, Bq4[kt].w);
                    mma16816(d[2][0], d[2][1], d[2][2], d[2][3],
                             a0, a1, a2, a3, Bq2[kt].x, Bq2[kt].y);
                }
                const int rr0 = mt * 16 + g, rr1 = rr0 + 8;
                #pragma unroll
                for (int j = 0; j < 3; ++j) {
                    const int col = (wid * 3 + j) * 8 + t * 2;
                    *(uint32_t*)(qkvs + rr0 * 200 + col) = packbf(d[j][0], d[j][1]);
                    *(uint32_t*)(qkvs + rr1 * 200 + col) = packbf(d[j][2], d[j][3]);
                }
            }
        }
        __syncthreads();

        // ---- attention: causal tile-skip, diagonal-only masking ----
        {
            const int h = wid >> 1;
            const int half = wid & 1;
            uint32_t k0b0, k0b1, k0b2, k0b3;
            {
                const int kr = ((lane & 16) >> 1) + (lane & 7);
                const int kc = 64 + h * 16 + (lane & 8);
                ldsm_x4(act_a + (uint32_t)((kr * 200 + kc) * 2), k0b0, k0b1, k0b2, k0b3);
            }
            uint32_t v0b0, v0b1, v0b2, v0b3;
            {
                const int vc = 128 + h * 16 + lc;
                ldsm_x4t(act_a + (uint32_t)((lr * 200 + vc) * 2), v0b0, v0b1, v0b2, v0b3);
            }
            #pragma unroll
            for (int mt = 0; mt < 2; ++mt) {
                const int rowbase = (mt == 0) ? half * 16 : 48 - half * 16;
                const int nact = (rowbase >> 4) + 1;
                uint32_t qa0, qa1, qa2, qa3;
                ldsm_x4(act_a + (uint32_t)(((rowbase + lr) * 200 + h * 16 + lc) * 2),
                        qa0, qa1, qa2, qa3);
                float s[8][4];
                #pragma unroll
                for (int jp = 0; jp < 4; ++jp) {
                    if (jp >= nact) continue;
                    uint32_t kb0, kb1, kb2, kb3;
                    if (jp == 0) {
                        kb0 = k0b0; kb1 = k0b1; kb2 = k0b2; kb3 = k0b3;
                    } else {
                        const int kr = jp * 16 + ((lane & 16) >> 1) + (lane & 7);
                        const int kc = 64 + h * 16 + (lane & 8);
                        ldsm_x4(act_a + (uint32_t)((kr * 200 + kc) * 2), kb0, kb1, kb2, kb3);
                    }
                    s[2 * jp][0] = s[2 * jp][1] = s[2 * jp][2] = s[2 * jp][3] = 0.f;
                    s[2 * jp + 1][0] = s[2 * jp + 1][1] = s[2 * jp + 1][2] = s[2 * jp + 1][3] = 0.f;
                    mma16816(s[2 * jp][0], s[2 * jp][1], s[2 * jp][2], s[2 * jp][3],
                             qa0, qa1, qa2, qa3, kb0, kb1);
                    mma16816(s[2 * jp + 1][0], s[2 * jp + 1][1], s[2 * jp + 1][2], s[2 * jp + 1][3],
                             qa0, qa1, qa2, qa3, kb2, kb3);
                }
                const int rA = rowbase + g, rB = rA + 8;
                const int diagj = 2 * (nact - 1);
                float mA = -1e30f, mB = -1e30f;
                #pragma unroll
                for (int j = 0; j < 8; ++j) {
                    if (j >= 2 * nact) continue;
                    if (j >= diagj) {
                        #pragma unroll
                        for (int e = 0; e < 2; ++e) {
                            const int col = j * 8 + t * 2 + e;
                            s[j][e]     = (col <= rA) ? s[j][e] * 0.25f     : -1e30f;
                            s[j][2 + e] = (col <= rB) ? s[j][2 + e] * 0.25f : -1e30f;
                            mA = fmaxf(mA, s[j][e]);
                            mB = fmaxf(mB, s[j][2 + e]);
                        }
                    } else {
                        #pragma unroll
                        for (int e = 0; e < 2; ++e) {
                            s[j][e]     *= 0.25f;
                            s[j][2 + e] *= 0.25f;
                            mA = fmaxf(mA, s[j][e]);
                            mB = fmaxf(mB, s[j][2 + e]);
                        }
                    }
                }
                mA = fmaxf(mA, __shfl_xor_sync(0xffffffffu, mA, 1));
                mA = fmaxf(mA, __shfl_xor_sync(0xffffffffu, mA, 2));
                mB = fmaxf(mB, __shfl_xor_sync(0xffffffffu, mB, 1));
                mB = fmaxf(mB, __shfl_xor_sync(0xffffffffu, mB, 2));
                float sA = 0.f, sB = 0.f;
                #pragma unroll
                for (int j = 0; j < 8; ++j) {
                    if (j >= 2 * nact) continue;
                    #pragma unroll
                    for (int e = 0; e < 2; ++e) {
                        s[j][e] = __expf(s[j][e] - mA);
                        s[j][2 + e] = __expf(s[j][2 + e] - mB);
                        sA += s[j][e];
                        sB += s[j][2 + e];
                    }
                }
                sA += __shfl_xor_sync(0xffffffffu, sA, 1);
                sA += __shfl_xor_sync(0xffffffffu, sA, 2);
                sB += __shfl_xor_sync(0xffffffffu, sB, 1);
                sB += __shfl_xor_sync(0xffffffffu, sB, 2);
                const float invA = 1.0f / sA, invB = 1.0f / sB;
                float y0[4] = {0.f, 0.f, 0.f, 0.f};
                float y1[4] = {0.f, 0.f, 0.f, 0.f};
                #pragma unroll
                for (int kk = 0; kk < 4; ++kk) {
                    if (kk >= nact) continue;
                    const uint32_t pa0 = packbf(s[2 * kk][0] * invA, s[2 * kk][1] * invA);
                    const uint32_t pa1 = packbf(s[2 * kk][2] * invB, s[2 * kk][3] * invB);
                    const uint32_t pa2 = packbf(s[2 * kk + 1][0] * invA, s[2 * kk + 1][1] * invA);
                    const uint32_t pa3 = packbf(s[2 * kk + 1][2] * invB, s[2 * kk + 1][3] * invB);
                    uint32_t vb0, vb1, vb2, vb3;
                    if (kk == 0) {
                        vb0 = v0b0; vb1 = v0b1; vb2 = v0b2; vb3 = v0b3;
                    } else {
                        const int vr = kk * 16 + lr;
                        const int vc = 128 + h * 16 + lc;
                        ldsm_x4t(act_a + (uint32_t)((vr * 200 + vc) * 2), vb0, vb1, vb2, vb3);
                    }
                    mma16816(y0[0], y0[1], y0[2], y0[3], pa0, pa1, pa2, pa3, vb0, vb1);
                    mma16816(y1[0], y1[1], y1[2], y1[3], pa0, pa1, pa2, pa3, vb2, vb3);
                }
                const int cy = h * 16 + t * 2;
                *(uint32_t*)(hb + (rowbase + g) * 72 + cy)         = packbf(y0[0], y0[1]);
                *(uint32_t*)(hb + (rowbase + g + 8) * 72 + cy)     = packbf(y0[2], y0[3]);
                *(uint32_t*)(hb + (rowbase + g) * 72 + cy + 8)     = packbf(y1[0], y1[1]);
                *(uint32_t*)(hb + (rowbase + g + 8) * 72 + cy + 8) = packbf(y1[2], y1[3]);
            }
        }

        // ---- PREFETCH: aproj B fragments + bias ----
        uint4 Bap4[4];
        #pragma unroll
        for (int kt = 0; kt < 4; ++kt)
            Bap4[kt] = __ldg(g_fap4 + ((kt * 4 + ng) << 5) + lane);
        float2 biasap[2];
        #pragma unroll
        for (int nl = 0; nl < 2; ++nl)
            biasap[nl] = *(const float2*)(aproj_b + (ng * 2 + nl) * 8 + t * 2);
        __syncthreads();

        // ---- attention proj + residual: 8 warps, 2m x 2n tiles ----
        {
            float d[2][2][4];
            #pragma unroll
            for (int nl = 0; nl < 2; ++nl) {
                #pragma unroll
                for (int ml = 0; ml < 2; ++ml) {
                    d[ml][nl][0] = d[ml][nl][2] = biasap[nl].x;
                    d[ml][nl][1] = d[ml][nl][3] = biasap[nl].y;
                }
            }
            #pragma unroll
            for (int kt = 0; kt < 4; ++kt) {
                uint32_t a[2][4];
                #pragma unroll
                for (int ml = 0; ml < 2; ++ml)
                    ldsm_x4(hb_a + (uint32_t)((((mg * 2 + ml) * 16 + lr) * 72 + kt * 16 + lc) * 2),
                            a[ml][0], a[ml][1], a[ml][2], a[ml][3]);
                #pragma unroll
                for (int ml = 0; ml < 2; ++ml) {
                    mma16816(d[ml][0][0], d[ml][0][1], d[ml][0][2], d[ml][0][3],
                             a[ml][0], a[ml][1], a[ml][2], a[ml][3],
                             Bap4[kt].x, Bap4[kt].y);
                    mma16816(d[ml][1][0], d[ml][1][1], d[ml][1][2], d[ml][1][3],
                             a[ml][0], a[ml][1], a[ml][2], a[ml][3],
                             Bap4[kt].z, Bap4[kt].w);
                }
            }
            #pragma unroll
            for (int ml = 0; ml < 2; ++ml) {
                const int rr0 = (mg * 2 + ml) * 16 + g, rr1 = rr0 + 8;
                #pragma unroll
                for (int nl = 0; nl < 2; ++nl) {
                    const int col = (ng * 2 + nl) * 8 + t * 2;
                    float2 v0 = *(float2*)(xs + rr0 * 64 + col);
                    float2 v1 = *(float2*)(xs + rr1 * 64 + col);
                    v0.x += d[ml][nl][0]; v0.y += d[ml][nl][1];
                    v1.x += d[ml][nl][2]; v1.y += d[ml][nl][3];
                    *(float2*)(xs + rr0 * 64 + col) = v0;
                    *(float2*)(xs + rr1 * 64 + col) = v1;
                }
            }
        }

        // ---- PREFETCH: FC B fragments + biases ----
        uint4 Bfc4[4][2];
        #pragma unroll
        for (int kt = 0; kt < 4; ++kt)
            #pragma unroll
            for (int p = 0; p < 2; ++p)
                Bfc4[kt][p] = __ldg(g_ffc4 + ((kt * 16 + wid * 2 + p) << 5) + lane);
        float2 biasfc[4];
        #pragma unroll
        for (int j = 0; j < 4; ++j)
            biasfc[j] = *(const float2*)(fc_b + (wid * 4 + j) * 8 + t * 2);
        __syncthreads();

        // ---- LN2 -> hb (uint2 stores) ----
        {
            const float4* src = (const float4*)(xs + lrow * 64 + lcol);
            float4 v4[4];
            float s = 0.f, s2 = 0.f;
            #pragma unroll
            for (int i = 0; i < 4; ++i) {
                v4[i] = src[i];
                s += v4[i].x + v4[i].y + v4[i].z + v4[i].w;
                s2 += v4[i].x * v4[i].x + v4[i].y * v4[i].y
                    + v4[i].z * v4[i].z + v4[i].w * v4[i].w;
            }
            s  += __shfl_xor_sync(0xffffffffu, s, 1);
            s2 += __shfl_xor_sync(0xffffffffu, s2, 1);
            s  += __shfl_xor_sync(0xffffffffu, s, 2);
            s2 += __shfl_xor_sync(0xffffffffu, s2, 2);
            const float mu = s * (1.0f / 64.0f);
            const float var = s2 * (1.0f / 64.0f) - mu * mu;
            const float rstd = rsqrtf(var + EPS_);
            const float* v = (const float*)v4;
            #pragma unroll
            for (int i = 0; i < 4; ++i) {
                const int c = lcol + 4 * i;
                uint2 u;
                u.x = packbf((v[4*i+0] - mu) * rstd * ln2_g[c+0] + ln2_b[c+0],
                             (v[4*i+1] - mu) * rstd * ln2_g[c+1] + ln2_b[c+1]);
                u.y = packbf((v[4*i+2] - mu) * rstd * ln2_g[c+2] + ln2_b[c+2],
                             (v[4*i+3] - mu) * rstd * ln2_g[c+3] + ln2_b[c+3]);
                *(uint2*)(hb + lrow * 72 + c) = u;
            }
        }
        __syncthreads();

        // ---- FC + GELU -> fcact (stride 264) ----
        __nv_bfloat16* fcact = qkvs;
        {
            #pragma unroll
            for (int mt = 0; mt < 4; ++mt) {
                float d[4][4];
                #pragma unroll
                for (int j = 0; j < 4; ++j) {
                    d[j][0] = d[j][2] = biasfc[j].x;
                    d[j][1] = d[j][3] = biasfc[j].y;
                }
                #pragma unroll
                for (int kt = 0; kt < 4; ++kt) {
                    uint32_t a0, a1, a2, a3;
                    ldsm_x4(hb_a + (uint32_t)(((mt * 16 + lr) * 72 + kt * 16 + lc) * 2),
                            a0, a1, a2, a3);
                    mma16816(d[0][0], d[0][1], d[0][2], d[0][3],
                             a0, a1, a2, a3, Bfc4[kt][0].x, Bfc4[kt][0].y);
                    mma16816(d[1][0], d[1][1], d[1][2], d[1][3],
                             a0, a1, a2, a3, Bfc4[kt][0].z, Bfc4[kt][0].w);
                    mma16816(d[2][0], d[2][1], d[2][2], d[2][3],
                             a0, a1, a2, a3, Bfc4[kt][1].x, Bfc4[kt][1].y);
                    mma16816(d[3][0], d[3][1], d[3][2], d[3][3],
                             a0, a1, a2, a3, Bfc4[kt][1].z, Bfc4[kt][1].w);
                }
                const int rr0 = mt * 16 + g, rr1 = rr0 + 8;
                #pragma unroll
                for (int j = 0; j < 4; ++j) {
                    const int col = (wid * 4 + j) * 8 + t * 2;
                    *(uint32_t*)(fcact + rr0 * 264 + col) =
                        packbf(gelu_fast(d[j][0]), gelu_fast(d[j][1]));
                    *(uint32_t*)(fcact + rr1 * 264 + col) =
                        packbf(gelu_fast(d[j][2]), gelu_fast(d[j][3]));
                }
            }
        }
        __syncthreads();

        // ---- MLP proj: 4 warps (one per SMSP), each 2m x 4n x 16kt ----
        if (wid < 4) {
            const int mg2 = wid & 1;
            const int ng2 = wid >> 1;
            float accO[2][4][4];
            #pragma unroll
            for (int nt = 0; nt < 4; ++nt) {
                const int col = (ng2 * 4 + nt) * 8 + t * 2;
                const float2 bb = *(const float2*)(mproj_b + col);
                #pragma unroll
                for (int ml = 0; ml < 2; ++ml) {
                    const int rr0 = (mg2 * 2 + ml) * 16 + g;
                    const float2 x0 = *(const float2*)(xs + rr0 * 64 + col);
                    const float2 x1 = *(const float2*)(xs + (rr0 + 8) * 64 + col);
                    accO[ml][nt][0] = bb.x + x0.x; accO[ml][nt][1] = bb.y + x0.y;
                    accO[ml][nt][2] = bb.x + x1.x; accO[ml][nt][3] = bb.y + x1.y;
                }
            }
            #pragma unroll
            for (int kt = 0; kt < 16; ++kt) {
                const uint4 p0 = __ldg(g_fmp4 + ((kt * 4 + ng2 * 2) << 5) + lane);
                const uint4 p1 = __ldg(g_fmp4 + ((kt * 4 + ng2 * 2 + 1) << 5) + lane);
                uint32_t a[2][4];
                #pragma unroll
                for (int ml = 0; ml < 2; ++ml)
                    ldsm_x4(act_a + (uint32_t)((((mg2 * 2 + ml) * 16 + lr) * 264 + kt * 16 + lc) * 2),
                            a[ml][0], a[ml][1], a[ml][2], a[ml][3]);
                #pragma unroll
                for (int ml = 0; ml < 2; ++ml) {
                    mma16816(accO[ml][0][0], accO[ml][0][1], accO[ml][0][2], accO[ml][0][3],
                             a[ml][0], a[ml][1], a[ml][2], a[ml][3], p0.x, p0.y);
                    mma16816(accO[ml][1][0], accO[ml][1][1], accO[ml][1][2], accO[ml][1][3],
                             a[ml][0], a[ml][1], a[ml][2], a[ml][3], p0.z, p0.w);
                    mma16816(accO[ml][2][0], accO[ml][2][1], accO[ml][2][2], accO[ml][2][3],
                             a[ml][0], a[ml][1], a[ml][2], a[ml][3], p1.x, p1.y);
                    mma16816(accO[ml][3][0], accO[ml][3][1], accO[ml][3][2], accO[ml][3][3],
                             a[ml][0], a[ml][1], a[ml][2], a[ml][3], p1.z, p1.w);
                }
            }
            #pragma unroll
            for (int ml = 0; ml < 2; ++ml) {
                const int rr0 = (mg2 * 2 + ml) * 16 + g, rr1 = rr0 + 8;
                #pragma unroll
                for (int nt = 0; nt < 4; ++nt) {
                    const int col = (ng2 * 4 + nt) * 8 + t * 2;
                    *(float2*)(og + rr0 * 64 + col) = make_float2(accO[ml][nt][0], accO[ml][nt][1]);
                    *(float2*)(og + rr1 * 64 + col) = make_float2(accO[ml][nt][2], accO[ml][nt][3]);
                }
            }
        }
    }
}

extern "C" void kernel_launch(void* const* d_in, const int* in_sizes, int n_in,
                              void* d_out, int out_size) {
    const float* x       = (const float*)d_in[0];
    const float* ln1_g   = (const float*)d_in[1];
    const float* ln1_b   = (const float*)d_in[2];
    const float* qkv_w   = (const float*)d_in[3];
    const float* qkv_b   = (const float*)d_in[4];
    const float* aproj_w = (const float*)d_in[5];
    const float* aproj_b = (const float*)d_in[6];
    const float* ln2_g   = (const float*)d_in[7];
    const float* ln2_b   = (const float*)d_in[8];
    const float* fc_w    = (const float*)d_in[9];
    const float* fc_b    = (const float*)d_in[10];
    const float* mproj_w = (const float*)d_in[11];
    const float* mproj_b = (const float*)d_in[12];
    float* out = (float*)d_out;

    const int B = in_sizes[0] / (T_ * C_);

    convert_weights_kernel<<<26, 256>>>(qkv_w, aproj_w, fc_w, mproj_w);

    cudaFuncSetAttribute(block_tc_kernel,
                         cudaFuncAttributeMaxDynamicSharedMemorySize, SMEM_BYTES);
    block_tc_kernel<<<PERSIST_CTAS, 256, SMEM_BYTES>>>(
        x, ln1_g, ln1_b, qkv_b, aproj_b, ln2_g, ln2_b, fc_b, mproj_b, out, B);
}

// round 16
// speedup vs baseline: 1.1557x; 1.1557x over previous
#include <cuda_runtime.h>
#include <cuda_bf16.h>
#include <math.h>
#include <stdint.h>

// Fused transformer block on tensor cores (bf16 mma.sync, fp32 accum).
// One CTA (256 thr = 8 warps) per batch element. B=4096, T=64, C=64, H=4, d=16.
// R16: revert persistent CTAs (R15 regression: the loop serialized inter-tile
// overlap the CTA scheduler gives for free). R14 base + log2e folded into the
// softmax scale (ex2.approx directly, no per-exp FMUL).

#define T_ 64
#define C_ 64
#define EPS_ 1e-5f

// ---------------- pair-packed bf16 weight fragments (prologue) --------------
__device__ uint4 g_fqkv4[4 * 8 * 32];   // qkv nt pairs {3w, 3w+1} per warp w
__device__ uint2 g_fqkv2[4 * 8 * 32];   // qkv nt {3w+2}
__device__ uint4 g_fap4 [4 * 4 * 32];   // aproj nt pairs
__device__ uint4 g_ffc4 [4 * 16 * 32];  // fc nt pairs
__device__ uint4 g_fmp4 [16 * 4 * 32];  // mproj nt pairs

__device__ __forceinline__ uint32_t packbf(float x, float y) {
    __nv_bfloat162 h = __floats2bfloat162_rn(x, y);
    return *(uint32_t*)&h;
}

__device__ __forceinline__ float ex2f(float x) {
    float r;
    asm("ex2.approx.f32 %0, %1;\n" : "=f"(r) : "f"(x));
    return r;
}

__device__ __forceinline__ uint2 make_frag(const float* __restrict__ W, int ld,
                                           int kt, int nt, int lane) {
    const int gid = lane >> 2, tig = lane & 3;
    const int k0 = kt * 16 + tig * 2, n = nt * 8 + gid;
    uint2 v;
    v.x = packbf(__ldg(W + k0 * ld + n), __ldg(W + (k0 + 1) * ld + n));
    v.y = packbf(__ldg(W + (k0 + 8) * ld + n), __ldg(W + (k0 + 9) * ld + n));
    return v;
}

// Flat work-item prologue: each thread produces exactly one fragment record.
__global__ void convert_weights_kernel(const float* __restrict__ qkv_w,
                                       const float* __restrict__ aproj_w,
                                       const float* __restrict__ fc_w,
                                       const float* __restrict__ mproj_w) {
    const int idx = blockIdx.x * blockDim.x + threadIdx.x;
    const int lane = idx & 31;
    if (idx < 1024) {
        const int rem = idx >> 5;
        const int kt = rem >> 3, w = rem & 7;
        const uint2 a = make_frag(qkv_w, 192, kt, w * 3 + 0, lane);
        const uint2 b = make_frag(qkv_w, 192, kt, w * 3 + 1, lane);
        g_fqkv4[idx] = make_uint4(a.x, a.y, b.x, b.y);
    } else if (idx < 2048) {
        const int i = idx - 1024;
        const int rem = i >> 5;
        const int kt = rem >> 3, w = rem & 7;
        g_fqkv2[i] = make_frag(qkv_w, 192, kt, w * 3 + 2, lane);
    } else if (idx < 2560) {
        const int i = idx - 2048;
        const int rem = i >> 5;
        const int kt = rem >> 2, p = rem & 3;
        const uint2 a = make_frag(aproj_w, 64, kt, p * 2 + 0, lane);
        const uint2 b = make_frag(aproj_w, 64, kt, p * 2 + 1, lane);
        g_fap4[i] = make_uint4(a.x, a.y, b.x, b.y);
    } else if (idx < 4608) {
        const int i = idx - 2560;
        const int rem = i >> 5;
        const int kt = rem >> 4, p = rem & 15;
        const uint2 a = make_frag(fc_w, 256, kt, p * 2 + 0, lane);
        const uint2 b = make_frag(fc_w, 256, kt, p * 2 + 1, lane);
        g_ffc4[i] = make_uint4(a.x, a.y, b.x, b.y);
    } else if (idx < 6656) {
        const int i = idx - 4608;
        const int rem = i >> 5;
        const int kt = rem >> 2, p = rem & 3;
        const uint2 a = make_frag(mproj_w, 64, kt, p * 2 + 0, lane);
        const uint2 b = make_frag(mproj_w, 64, kt, p * 2 + 1, lane);
        g_fmp4[i] = make_uint4(a.x, a.y, b.x, b.y);
    }
}

// ---------------- helpers ----------------------------------------------------
__device__ __forceinline__ uint32_t smem_u32(const void* p) {
    return (uint32_t)__cvta_generic_to_shared(p);
}
__device__ __forceinline__ void ldsm_x4(uint32_t a, uint32_t& r0, uint32_t& r1,
                                        uint32_t& r2, uint32_t& r3) {
    asm volatile("ldmatrix.sync.aligned.m8n8.x4.shared.b16 {%0,%1,%2,%3}, [%4];\n"
                 : "=r"(r0), "=r"(r1), "=r"(r2), "=r"(r3) : "r"(a));
}
__device__ __forceinline__ void ldsm_x4t(uint32_t a, uint32_t& r0, uint32_t& r1,
                                         uint32_t& r2, uint32_t& r3) {
    asm volatile("ldmatrix.sync.aligned.m8n8.x4.trans.shared.b16 {%0,%1,%2,%3}, [%4];\n"
                 : "=r"(r0), "=r"(r1), "=r"(r2), "=r"(r3) : "r"(a));
}
__device__ __forceinline__ void mma16816(float& d0, float& d1, float& d2, float& d3,
                                         uint32_t a0, uint32_t a1, uint32_t a2,
                                         uint32_t a3, uint32_t b0, uint32_t b1) {
    asm volatile(
        "mma.sync.aligned.m16n8k16.row.col.f32.bf16.bf16.f32 "
        "{%0,%1,%2,%3},{%4,%5,%6,%7},{%8,%9},{%0,%1,%2,%3};\n"
        : "+f"(d0), "+f"(d1), "+f"(d2), "+f"(d3)
        : "r"(a0), "r"(a1), "r"(a2), "r"(a3), "r"(b0), "r"(b1));
}
__device__ __forceinline__ float gelu_fast(float v) {
    float u = v * (0.7978845608f + 0.0356774081f * v * v);
    float th;
    asm("tanh.approx.f32 %0, %1;\n" : "=f"(th) : "f"(u));
    return 0.5f * v * (1.0f + th);
}

// smem: xs fp32 16384 | hb 64x72 bf16 9216 | act bf16 (qkv 64x200 / fc 64x264)
#define OFF_XS 0
#define OFF_HB 16384
#define OFF_ACT 25600
#define SMEM_BYTES (25600 + 64 * 264 * 2)   // 59392

// softmax scale folded with log2(e): 0.25 * 1.44269504
#define SM_SCALE 0.360673760222f

__global__ __launch_bounds__(256, 3) void block_tc_kernel(
    const float* __restrict__ x,
    const float* __restrict__ ln1_g, const float* __restrict__ ln1_b,
    const float* __restrict__ qkv_b,
    const float* __restrict__ aproj_b,
    const float* __restrict__ ln2_g, const float* __restrict__ ln2_b,
    const float* __restrict__ fc_b,
    const float* __restrict__ mproj_b,
    float* __restrict__ out) {
    extern __shared__ char smem[];
    float* xs = (float*)(smem + OFF_XS);
    __nv_bfloat16* hb = (__nv_bfloat16*)(smem + OFF_HB);      // stride 72
    __nv_bfloat16* qkvs = (__nv_bfloat16*)(smem + OFF_ACT);   // stride 200 / 264
    const uint32_t hb_a = smem_u32(hb);
    const uint32_t act_a = smem_u32(qkvs);

    const int tid = threadIdx.x;
    const int wid = tid >> 5;
    const int lane = tid & 31;
    const int g = lane >> 2;
    const int t = lane & 3;
    const int lr = lane & 15;             // ldsm row-in-tile
    const int lc = (lane >> 4) << 3;      // ldsm col offset
    const int mg = wid & 1;               // 2m x 2n partition (aproj)
    const int ng = wid >> 1;

    const size_t base = (size_t)blockIdx.x * (T_ * C_);
    const float* xg = x + base;
    float* og = out + base;

    const int lrow = tid >> 2;            // LN row
    const int lcol = (tid & 3) * 16;      // LN col base

    // ---- PREFETCH: QKV B fragments + biases ----
    uint4 Bq4[4];
    uint2 Bq2[4];
    #pragma unroll
    for (int kt = 0; kt < 4; ++kt) {
        Bq4[kt] = __ldg(g_fqkv4 + ((kt * 8 + wid) << 5) + lane);
        Bq2[kt] = __ldg(g_fqkv2 + ((kt * 8 + wid) << 5) + lane);
    }
    float2 biasq[3];
    #pragma unroll
    for (int j = 0; j < 3; ++j)
        biasq[j] = *(const float2*)(qkv_b + (wid * 3 + j) * 8 + t * 2);

    // ---- LN1 fused with global x read: x -> regs -> xs + hb ----
    {
        const float4* srcg = (const float4*)(xg + lrow * 64 + lcol);
        float4 v4[4];
        float s = 0.f, s2 = 0.f;
        #pragma unroll
        for (int i = 0; i < 4; ++i) {
            v4[i] = srcg[i];
            s += v4[i].x + v4[i].y + v4[i].z + v4[i].w;
            s2 += v4[i].x * v4[i].x + v4[i].y * v4[i].y
                + v4[i].z * v4[i].z + v4[i].w * v4[i].w;
        }
        s  += __shfl_xor_sync(0xffffffffu, s, 1);
        s2 += __shfl_xor_sync(0xffffffffu, s2, 1);
        s  += __shfl_xor_sync(0xffffffffu, s, 2);
        s2 += __shfl_xor_sync(0xffffffffu, s2, 2);
        const float mu = s * (1.0f / 64.0f);
        const float var = s2 * (1.0f / 64.0f) - mu * mu;
        const float rstd = rsqrtf(var + EPS_);
        const float* v = (const float*)v4;
        #pragma unroll
        for (int i = 0; i < 4; ++i) {
            *(float4*)(xs + lrow * 64 + lcol + 4 * i) = v4[i];
            const int c = lcol + 4 * i;
            uint2 u;
            u.x = packbf((v[4*i+0] - mu) * rstd * ln1_g[c+0] + ln1_b[c+0],
                         (v[4*i+1] - mu) * rstd * ln1_g[c+1] + ln1_b[c+1]);
            u.y = packbf((v[4*i+2] - mu) * rstd * ln1_g[c+2] + ln1_b[c+2],
                         (v[4*i+3] - mu) * rstd * ln1_g[c+3] + ln1_b[c+3]);
            *(uint2*)(hb + lrow * 72 + c) = u;
        }
    }
    __syncthreads();

    // ---- QKV: warp owns cols [24w, 24w+24), loops all 4 m-tiles ----
    {
        #pragma unroll
        for (int mt = 0; mt < 4; ++mt) {
            float d[3][4];
            #pragma unroll
            for (int j = 0; j < 3; ++j) {
                d[j][0] = d[j][2] = biasq[j].x;
                d[j][1] = d[j][3] = biasq[j].y;
            }
            #pragma unroll
            for (int kt = 0; kt < 4; ++kt) {
                uint32_t a0, a1, a2, a3;
                ldsm_x4(hb_a + (uint32_t)(((mt * 16 + lr) * 72 + kt * 16 + lc) * 2),
                        a0, a1, a2, a3);
                mma16816(d[0][0], d[0][1], d[0][2], d[0][3],
                         a0, a1, a2, a3, Bq4[kt].x, Bq4[kt].y);
                mma16816(d[1][0], d[1][1], d[1][2], d[1][3],
                         a0, a1, a2, a3, Bq4[kt].z, Bq4[kt].w);
                mma16816(d[2][0], d[2][1], d[2][2], d[2][3],
                         a0, a1, a2, a3, Bq2[kt].x, Bq2[kt].y);
            }
            const int rr0 = mt * 16 + g, rr1 = rr0 + 8;
            #pragma unroll
            for (int j = 0; j < 3; ++j) {
                const int col = (wid * 3 + j) * 8 + t * 2;
                *(uint32_t*)(qkvs + rr0 * 200 + col) = packbf(d[j][0], d[j][1]);
                *(uint32_t*)(qkvs + rr1 * 200 + col) = packbf(d[j][2], d[j][3]);
            }
        }
    }
    __syncthreads();

    // ---- attention: causal tile-skip, diagonal-only masking, ex2 softmax ----
    {
        const int h = wid >> 1;
        const int half = wid & 1;
        uint32_t k0b0, k0b1, k0b2, k0b3;
        {
            const int kr = ((lane & 16) >> 1) + (lane & 7);
            const int kc = 64 + h * 16 + (lane & 8);
            ldsm_x4(act_a + (uint32_t)((kr * 200 + kc) * 2), k0b0, k0b1, k0b2, k0b3);
        }
        uint32_t v0b0, v0b1, v0b2, v0b3;
        {
            const int vc = 128 + h * 16 + lc;
            ldsm_x4t(act_a + (uint32_t)((lr * 200 + vc) * 2), v0b0, v0b1, v0b2, v0b3);
        }
        #pragma unroll
        for (int mt = 0; mt < 2; ++mt) {
            const int rowbase = (mt == 0) ? half * 16 : 48 - half * 16;
            const int nact = (rowbase >> 4) + 1;   // active 16-wide key tiles
            uint32_t qa0, qa1, qa2, qa3;
            ldsm_x4(act_a + (uint32_t)(((rowbase + lr) * 200 + h * 16 + lc) * 2),
                    qa0, qa1, qa2, qa3);
            float s[8][4];
            #pragma unroll
            for (int jp = 0; jp < 4; ++jp) {
                if (jp >= nact) continue;            // warp-uniform skip
                uint32_t kb0, kb1, kb2, kb3;
                if (jp == 0) {
                    kb0 = k0b0; kb1 = k0b1; kb2 = k0b2; kb3 = k0b3;
                } else {
                    const int kr = jp * 16 + ((lane & 16) >> 1) + (lane & 7);
                    const int kc = 64 + h * 16 + (lane & 8);
                    ldsm_x4(act_a + (uint32_t)((kr * 200 + kc) * 2), kb0, kb1, kb2, kb3);
                }
                s[2 * jp][0] = s[2 * jp][1] = s[2 * jp][2] = s[2 * jp][3] = 0.f;
                s[2 * jp + 1][0] = s[2 * jp + 1][1] = s[2 * jp + 1][2] = s[2 * jp + 1][3] = 0.f;
                mma16816(s[2 * jp][0], s[2 * jp][1], s[2 * jp][2], s[2 * jp][3],
                         qa0, qa1, qa2, qa3, kb0, kb1);
                mma16816(s[2 * jp + 1][0], s[2 * jp + 1][1], s[2 * jp + 1][2], s[2 * jp + 1][3],
                         qa0, qa1, qa2, qa3, kb2, kb3);
            }
            const int rA = rowbase + g, rB = rA + 8;
            const int diagj = 2 * (nact - 1);
            float mA = -1e30f, mB = -1e30f;
            #pragma unroll
            for (int j = 0; j < 8; ++j) {
                if (j >= 2 * nact) continue;
                if (j >= diagj) {
                    #pragma unroll
                    for (int e = 0; e < 2; ++e) {
                        const int col = j * 8 + t * 2 + e;
                        s[j][e]     = (col <= rA) ? s[j][e] * SM_SCALE     : -1e30f;
                        s[j][2 + e] = (col <= rB) ? s[j][2 + e] * SM_SCALE : -1e30f;
                        mA = fmaxf(mA, s[j][e]);
                        mB = fmaxf(mB, s[j][2 + e]);
                    }
                } else {
                    #pragma unroll
                    for (int e = 0; e < 2; ++e) {
                        s[j][e]     *= SM_SCALE;
                        s[j][2 + e] *= SM_SCALE;
                        mA = fmaxf(mA, s[j][e]);
                        mB = fmaxf(mB, s[j][2 + e]);
                    }
                }
            }
            mA = fmaxf(mA, __shfl_xor_sync(0xffffffffu, mA, 1));
            mA = fmaxf(mA, __shfl_xor_sync(0xffffffffu, mA, 2));
            mB = fmaxf(mB, __shfl_xor_sync(0xffffffffu, mB, 1));
            mB = fmaxf(mB, __shfl_xor_sync(0xffffffffu, mB, 2));
            float sA = 0.f, sB = 0.f;
            #pragma unroll
            for (int j = 0; j < 8; ++j) {
                if (j >= 2 * nact) continue;
                #pragma unroll
                for (int e = 0; e < 2; ++e) {
                    s[j][e] = ex2f(s[j][e] - mA);
                    s[j][2 + e] = ex2f(s[j][2 + e] - mB);
                    sA += s[j][e];
                    sB += s[j][2 + e];
                }
            }
            sA += __shfl_xor_sync(0xffffffffu, sA, 1);
            sA += __shfl_xor_sync(0xffffffffu, sA, 2);
            sB += __shfl_xor_sync(0xffffffffu, sB, 1);
            sB += __shfl_xor_sync(0xffffffffu, sB, 2);
            const float invA = 1.0f / sA, invB = 1.0f / sB;
            float y0[4] = {0.f, 0.f, 0.f, 0.f};
            float y1[4] = {0.f, 0.f, 0.f, 0.f};
            #pragma unroll
            for (int kk = 0; kk < 4; ++kk) {
                if (kk >= nact) continue;
                const uint32_t pa0 = packbf(s[2 * kk][0] * invA, s[2 * kk][1] * invA);
                const uint32_t pa1 = packbf(s[2 * kk][2] * invB, s[2 * kk][3] * invB);
                const uint32_t pa2 = packbf(s[2 * kk + 1][0] * invA, s[2 * kk + 1][1] * invA);
                const uint32_t pa3 = packbf(s[2 * kk + 1][2] * invB, s[2 * kk + 1][3] * invB);
                uint32_t vb0, vb1, vb2, vb3;
                if (kk == 0) {
                    vb0 = v0b0; vb1 = v0b1; vb2 = v0b2; vb3 = v0b3;
                } else {
                    const int vr = kk * 16 + lr;
                    const int vc = 128 + h * 16 + lc;
                    ldsm_x4t(act_a + (uint32_t)((vr * 200 + vc) * 2), vb0, vb1, vb2, vb3);
                }
                mma16816(y0[0], y0[1], y0[2], y0[3], pa0, pa1, pa2, pa3, vb0, vb1);
                mma16816(y1[0], y1[1], y1[2], y1[3], pa0, pa1, pa2, pa3, vb2, vb3);
            }
            const int cy = h * 16 + t * 2;
            *(uint32_t*)(hb + (rowbase + g) * 72 + cy)         = packbf(y0[0], y0[1]);
            *(uint32_t*)(hb + (rowbase + g + 8) * 72 + cy)     = packbf(y0[2], y0[3]);
            *(uint32_t*)(hb + (rowbase + g) * 72 + cy + 8)     = packbf(y1[0], y1[1]);
            *(uint32_t*)(hb + (rowbase + g + 8) * 72 + cy + 8) = packbf(y1[2], y1[3]);
        }
    }

    // ---- PREFETCH: aproj B fragments + bias ----
    uint4 Bap4[4];
    #pragma unroll
    for (int kt = 0; kt < 4; ++kt)
        Bap4[kt] = __ldg(g_fap4 + ((kt * 4 + ng) << 5) + lane);
    float2 biasap[2];
    #pragma unroll
    for (int nl = 0; nl < 2; ++nl)
        biasap[nl] = *(const float2*)(aproj_b + (ng * 2 + nl) * 8 + t * 2);
    __syncthreads();

    // ---- attention proj + residual: 8 warps, 2m x 2n tiles ----
    {
        float d[2][2][4];
        #pragma unroll
        for (int nl = 0; nl < 2; ++nl) {
            #pragma unroll
            for (int ml = 0; ml < 2; ++ml) {
                d[ml][nl][0] = d[ml][nl][2] = biasap[nl].x;
                d[ml][nl][1] = d[ml][nl][3] = biasap[nl].y;
            }
        }
        #pragma unroll
        for (int kt = 0; kt < 4; ++kt) {
            uint32_t a[2][4];
            #pragma unroll
            for (int ml = 0; ml < 2; ++ml)
                ldsm_x4(hb_a + (uint32_t)((((mg * 2 + ml) * 16 + lr) * 72 + kt * 16 + lc) * 2),
                        a[ml][0], a[ml][1], a[ml][2], a[ml][3]);
            #pragma unroll
            for (int ml = 0; ml < 2; ++ml) {
                mma16816(d[ml][0][0], d[ml][0][1], d[ml][0][2], d[ml][0][3],
                         a[ml][0], a[ml][1], a[ml][2], a[ml][3],
                         Bap4[kt].x, Bap4[kt].y);
                mma16816(d[ml][1][0], d[ml][1][1], d[ml][1][2], d[ml][1][3],
                         a[ml][0], a[ml][1], a[ml][2], a[ml][3],
                         Bap4[kt].z, Bap4[kt].w);
            }
        }
        #pragma unroll
        for (int ml = 0; ml < 2; ++ml) {
            const int rr0 = (mg * 2 + ml) * 16 + g, rr1 = rr0 + 8;
            #pragma unroll
            for (int nl = 0; nl < 2; ++nl) {
                const int col = (ng * 2 + nl) * 8 + t * 2;
                float2 v0 = *(float2*)(xs + rr0 * 64 + col);
                float2 v1 = *(float2*)(xs + rr1 * 64 + col);
                v0.x += d[ml][nl][0]; v0.y += d[ml][nl][1];
                v1.x += d[ml][nl][2]; v1.y += d[ml][nl][3];
                *(float2*)(xs + rr0 * 64 + col) = v0;
                *(float2*)(xs + rr1 * 64 + col) = v1;
            }
        }
    }

    // ---- PREFETCH: FC B fragments + biases ----
    uint4 Bfc4[4][2];
    #pragma unroll
    for (int kt = 0; kt < 4; ++kt)
        #pragma unroll
        for (int p = 0; p < 2; ++p)
            Bfc4[kt][p] = __ldg(g_ffc4 + ((kt * 16 + wid * 2 + p) << 5) + lane);
    float2 biasfc[4];
    #pragma unroll
    for (int j = 0; j < 4; ++j)
        biasfc[j] = *(const float2*)(fc_b + (wid * 4 + j) * 8 + t * 2);
    __syncthreads();

    // ---- LN2 -> hb (uint2 stores) ----
    {
        const float4* src = (const float4*)(xs + lrow * 64 + lcol);
        float4 v4[4];
        float s = 0.f, s2 = 0.f;
        #pragma unroll
        for (int i = 0; i < 4; ++i) {
            v4[i] = src[i];
            s += v4[i].x + v4[i].y + v4[i].z + v4[i].w;
            s2 += v4[i].x * v4[i].x + v4[i].y * v4[i].y
                + v4[i].z * v4[i].z + v4[i].w * v4[i].w;
        }
        s  += __shfl_xor_sync(0xffffffffu, s, 1);
        s2 += __shfl_xor_sync(0xffffffffu, s2, 1);
        s  += __shfl_xor_sync(0xffffffffu, s, 2);
        s2 += __shfl_xor_sync(0xffffffffu, s2, 2);
        const float mu = s * (1.0f / 64.0f);
        const float var = s2 * (1.0f / 64.0f) - mu * mu;
        const float rstd = rsqrtf(var + EPS_);
        const float* v = (const float*)v4;
        #pragma unroll
        for (int i = 0; i < 4; ++i) {
            const int c = lcol + 4 * i;
            uint2 u;
            u.x = packbf((v[4*i+0] - mu) * rstd * ln2_g[c+0] + ln2_b[c+0],
                         (v[4*i+1] - mu) * rstd * ln2_g[c+1] + ln2_b[c+1]);
            u.y = packbf((v[4*i+2] - mu) * rstd * ln2_g[c+2] + ln2_b[c+2],
                         (v[4*i+3] - mu) * rstd * ln2_g[c+3] + ln2_b[c+3]);
            *(uint2*)(hb + lrow * 72 + c) = u;
        }
    }
    __syncthreads();

    // ---- FC + GELU: warp owns cols [32w, 32w+32) of 256 -> fcact (stride 264)
    __nv_bfloat16* fcact = qkvs;
    {
        #pragma unroll
        for (int mt = 0; mt < 4; ++mt) {
            float d[4][4];
            #pragma unroll
            for (int j = 0; j < 4; ++j) {
                d[j][0] = d[j][2] = biasfc[j].x;
                d[j][1] = d[j][3] = biasfc[j].y;
            }
            #pragma unroll
            for (int kt = 0; kt < 4; ++kt) {
                uint32_t a0, a1, a2, a3;
                ldsm_x4(hb_a + (uint32_t)(((mt * 16 + lr) * 72 + kt * 16 + lc) * 2),
                        a0, a1, a2, a3);
                mma16816(d[0][0], d[0][1], d[0][2], d[0][3],
                         a0, a1, a2, a3, Bfc4[kt][0].x, Bfc4[kt][0].y);
                mma16816(d[1][0], d[1][1], d[1][2], d[1][3],
                         a0, a1, a2, a3, Bfc4[kt][0].z, Bfc4[kt][0].w);
                mma16816(d[2][0], d[2][1], d[2][2], d[2][3],
                         a0, a1, a2, a3, Bfc4[kt][1].x, Bfc4[kt][1].y);
                mma16816(d[3][0], d[3][1], d[3][2], d[3][3],
                         a0, a1, a2, a3, Bfc4[kt][1].z, Bfc4[kt][1].w);
            }
            const int rr0 = mt * 16 + g, rr1 = rr0 + 8;
            #pragma unroll
            for (int j = 0; j < 4; ++j) {
                const int col = (wid * 4 + j) * 8 + t * 2;
                *(uint32_t*)(fcact + rr0 * 264 + col) =
                    packbf(gelu_fast(d[j][0]), gelu_fast(d[j][1]));
                *(uint32_t*)(fcact + rr1 * 264 + col) =
                    packbf(gelu_fast(d[j][2]), gelu_fast(d[j][3]));
            }
        }
    }
    __syncthreads();

    // ---- MLP proj: 4 warps (one per SMSP), each 2m x 4n x 16kt ----
    if (wid < 4) {
        const int mg2 = wid & 1;
        const int ng2 = wid >> 1;
        float accO[2][4][4];
        #pragma unroll
        for (int nt = 0; nt < 4; ++nt) {
            const int col = (ng2 * 4 + nt) * 8 + t * 2;
            const float2 bb = *(const float2*)(mproj_b + col);
            #pragma unroll
            for (int ml = 0; ml < 2; ++ml) {
                const int rr0 = (mg2 * 2 + ml) * 16 + g;
                const float2 x0 = *(const float2*)(xs + rr0 * 64 + col);
                const float2 x1 = *(const float2*)(xs + (rr0 + 8) * 64 + col);
                accO[ml][nt][0] = bb.x + x0.x; accO[ml][nt][1] = bb.y + x0.y;
                accO[ml][nt][2] = bb.x + x1.x; accO[ml][nt][3] = bb.y + x1.y;
            }
        }
        #pragma unroll
        for (int kt = 0; kt < 16; ++kt) {
            const uint4 p0 = __ldg(g_fmp4 + ((kt * 4 + ng2 * 2) << 5) + lane);
            const uint4 p1 = __ldg(g_fmp4 + ((kt * 4 + ng2 * 2 + 1) << 5) + lane);
            uint32_t a[2][4];
            #pragma unroll
            for (int ml = 0; ml < 2; ++ml)
                ldsm_x4(act_a + (uint32_t)((((mg2 * 2 + ml) * 16 + lr) * 264 + kt * 16 + lc) * 2),
                        a[ml][0], a[ml][1], a[ml][2], a[ml][3]);
            #pragma unroll
            for (int ml = 0; ml < 2; ++ml) {
                mma16816(accO[ml][0][0], accO[ml][0][1], accO[ml][0][2], accO[ml][0][3],
                         a[ml][0], a[ml][1], a[ml][2], a[ml][3], p0.x, p0.y);
                mma16816(accO[ml][1][0], accO[ml][1][1], accO[ml][1][2], accO[ml][1][3],
                         a[ml][0], a[ml][1], a[ml][2], a[ml][3], p0.z, p0.w);
                mma16816(accO[ml][2][0], accO[ml][2][1], accO[ml][2][2], accO[ml][2][3],
                         a[ml][0], a[ml][1], a[ml][2], a[ml][3], p1.x, p1.y);
                mma16816(accO[ml][3][0], accO[ml][3][1], accO[ml][3][2], accO[ml][3][3],
                         a[ml][0], a[ml][1], a[ml][2], a[ml][3], p1.z, p1.w);
            }
        }
        // ---- store output ----
        #pragma unroll
        for (int ml = 0; ml < 2; ++ml) {
            const int rr0 = (mg2 * 2 + ml) * 16 + g, rr1 = rr0 + 8;
            #pragma unroll
            for (int nt = 0; nt < 4; ++nt) {
                const int col = (ng2 * 4 + nt) * 8 + t * 2;
                *(float2*)(og + rr0 * 64 + col) = make_float2(accO[ml][nt][0], accO[ml][nt][1]);
                *(float2*)(og + rr1 * 64 + col) = make_float2(accO[ml][nt][2], accO[ml][nt][3]);
            }
        }
    }
}

extern "C" void kernel_launch(void* const* d_in, const int* in_sizes, int n_in,
                              void* d_out, int out_size) {
    const float* x       = (const float*)d_in[0];
    const float* ln1_g   = (const float*)d_in[1];
    const float* ln1_b   = (const float*)d_in[2];
    const float* qkv_w   = (const float*)d_in[3];
    const float* qkv_b   = (const float*)d_in[4];
    const float* aproj_w = (const float*)d_in[5];
    const float* aproj_b = (const float*)d_in[6];
    const float* ln2_g   = (const float*)d_in[7];
    const float* ln2_b   = (const float*)d_in[8];
    const float* fc_w    = (const float*)d_in[9];
    const float* fc_b    = (const float*)d_in[10];
    const float* mproj_w = (const float*)d_in[11];
    const float* mproj_b = (const float*)d_in[12];
    float* out = (float*)d_out;

    const int B = in_sizes[0] / (T_ * C_);

    convert_weights_kernel<<<26, 256>>>(qkv_w, aproj_w, fc_w, mproj_w);

    cudaFuncSetAttribute(block_tc_kernel,
                         cudaFuncAttributeMaxDynamicSharedMemorySize, SMEM_BYTES);
    block_tc_kernel<<<B, 256, SMEM_BYTES>>>(
        x, ln1_g, ln1_b, qkv_b, aproj_b, ln2_g, ln2_b, fc_b, mproj_b, out);
}